// round 2
// baseline (speedup 1.0000x reference)
#include <cuda_runtime.h>

// Shapes (fixed for this problem)
#define B_ 32
#define P_ 196
#define D_ 512
#define H_ 8
#define U_ 4
#define C_ 500

#define KNOWN_ELEMS (B_ * C_ * (H_ + 3) * D_)   // 90,112,000
#define UNK_ELEMS   (B_ * (U_ + 3) * D_)        // 114,688
#define SEM_ELEMS   (B_ * H_ * D_)              // 131,072

// Scratch (device globals — no allocation allowed)
__device__ float g_dom[B_ * D_];        // projected_domain
__device__ float g_sem[B_ * H_ * D_];   // projected_sem

// ---------------------------------------------------------------------------
// Kernel 1: scores = patch·query, softmax over P, semantic = w·patch
// grid = B_, block = 512 (one thread per d in phase C)
// ---------------------------------------------------------------------------
__global__ __launch_bounds__(512) void k_attn(const float* __restrict__ patch,
                                              const float* __restrict__ query,
                                              float* __restrict__ sem_out) {
    __shared__ float q_sh[H_ * D_];     // 16 KB
    __shared__ float s_sh[P_ * H_];     // scores -> weights, 6.1 KB
    __shared__ float red_m[H_], red_s[H_];

    const int b   = blockIdx.x;
    const int tid = threadIdx.x;
    const int warp = tid >> 5, lane = tid & 31;
    const float* pb = patch + (size_t)b * P_ * D_;

    for (int i = tid; i < H_ * D_; i += 512) q_sh[i] = query[i];
    __syncthreads();

    // Phase A: warp per patch row p; 8 query dots simultaneously
    for (int p = warp; p < P_; p += 16) {
        float acc[H_];
#pragma unroll
        for (int h = 0; h < H_; h++) acc[h] = 0.f;
        const float* row = pb + p * D_;
        for (int d = lane; d < D_; d += 32) {
            float x = row[d];
#pragma unroll
            for (int h = 0; h < H_; h++) acc[h] = fmaf(x, q_sh[h * D_ + d], acc[h]);
        }
#pragma unroll
        for (int h = 0; h < H_; h++) {
#pragma unroll
            for (int o = 16; o; o >>= 1)
                acc[h] += __shfl_xor_sync(0xffffffffu, acc[h], o);
        }
        if (lane == 0) {
#pragma unroll
            for (int h = 0; h < H_; h++) s_sh[p * H_ + h] = acc[h];
        }
    }
    __syncthreads();

    // Phase B: softmax stats per head (warps 0..7)
    if (warp < H_) {
        float m = -1e30f;
        for (int p = lane; p < P_; p += 32) m = fmaxf(m, s_sh[p * H_ + warp]);
#pragma unroll
        for (int o = 16; o; o >>= 1) m = fmaxf(m, __shfl_xor_sync(0xffffffffu, m, o));
        float s = 0.f;
        for (int p = lane; p < P_; p += 32) s += __expf(s_sh[p * H_ + warp] - m);
#pragma unroll
        for (int o = 16; o; o >>= 1) s += __shfl_xor_sync(0xffffffffu, s, o);
        if (lane == 0) { red_m[warp] = m; red_s[warp] = 1.f / s; }
    }
    __syncthreads();

    for (int i = tid; i < P_ * H_; i += 512) {
        int h = i & (H_ - 1);
        s_sh[i] = __expf(s_sh[i] - red_m[h]) * red_s[h];
    }
    __syncthreads();

    // Phase C: thread d accumulates all 8 heads
    {
        const int d = tid;
        float acc[H_];
#pragma unroll
        for (int h = 0; h < H_; h++) acc[h] = 0.f;
        for (int p = 0; p < P_; p++) {
            float x = pb[p * D_ + d];
#pragma unroll
            for (int h = 0; h < H_; h++) acc[h] = fmaf(s_sh[p * H_ + h], x, acc[h]);
        }
#pragma unroll
        for (int h = 0; h < H_; h++)
            sem_out[((size_t)b * H_ + h) * D_ + d] = acc[h];
    }
}

// ---------------------------------------------------------------------------
// Kernel 2: projected_domain[b,e] = dom_b[e] + sum_d gf[b,d]*dom_W[e,d]
// grid = B_, block = 256 (warp per output row, float4 coalesced)
// ---------------------------------------------------------------------------
__global__ __launch_bounds__(256) void k_dom(const float* __restrict__ gf,
                                             const float* __restrict__ W,
                                             const float* __restrict__ bias) {
    __shared__ float4 g_sh[D_ / 4];
    const int b = blockIdx.x, tid = threadIdx.x;
    const float4* gin = (const float4*)(gf + b * D_);
    for (int i = tid; i < D_ / 4; i += 256) g_sh[i] = gin[i];
    __syncthreads();

    const int warp = tid >> 5, lane = tid & 31;
    for (int e = warp; e < D_; e += 8) {
        const float4* wr = (const float4*)(W + (size_t)e * D_);
        float acc = 0.f;
        for (int i = lane; i < D_ / 4; i += 32) {
            float4 w = wr[i], g = g_sh[i];
            acc += w.x * g.x + w.y * g.y + w.z * g.z + w.w * g.w;
        }
#pragma unroll
        for (int o = 16; o; o >>= 1) acc += __shfl_xor_sync(0xffffffffu, acc, o);
        if (lane == 0) g_dom[b * D_ + e] = acc + bias[e];
    }
}

// ---------------------------------------------------------------------------
// Kernel 3: projected_sem[b,h,e] = sem_b[h,e] + sum_d T[b,h,d]*sem_W[h,e,d]
// Tiled so sem_W is read exactly once from DRAM.
// grid = (32 e-tiles of 16, H_ heads), block = 256 (16 e x 16 b-pairs)
// dyn smem: T (32 x 516 padded) + W-tile (16 x 516 padded) = 99072 B
// ---------------------------------------------------------------------------
#define TPAD 516
__global__ __launch_bounds__(256) void k_sem(const float* __restrict__ sem_tok,
                                             const float* __restrict__ W,
                                             const float* __restrict__ bias) {
    extern __shared__ float sh[];
    float* Tsh = sh;                  // [32][TPAD]
    float* Wsh = sh + 32 * TPAD;      // [16][TPAD]

    const int h  = blockIdx.y;
    const int e0 = blockIdx.x * 16;
    const int tid = threadIdx.x;

    // Load all 32 batches' token vectors for head h (from d_out sem region)
    for (int i = tid; i < 32 * 128; i += 256) {
        int b = i >> 7, j = i & 127;
        ((float4*)(Tsh + b * TPAD))[j] =
            ((const float4*)sem_tok)[(size_t)(b * H_ + h) * 128 + j];
    }
    // Load 16-row W tile: W[h, e0..e0+15, :]
    const float4* wsrc = (const float4*)(W + ((size_t)h * D_ + e0) * D_);
    for (int i = tid; i < 16 * 128; i += 256) {
        int e = i >> 7, j = i & 127;
        ((float4*)(Wsh + e * TPAD))[j] = wsrc[e * 128 + j];
    }
    __syncthreads();

    const int e_local = tid & 15;
    const int bb      = tid >> 4;   // 0..15, handles b = bb and bb+16
    const float4* wrow = (const float4*)(Wsh + e_local * TPAD);
    const float4* t0   = (const float4*)(Tsh + bb * TPAD);
    const float4* t1   = (const float4*)(Tsh + (bb + 16) * TPAD);

    float a0 = 0.f, a1 = 0.f;
#pragma unroll 8
    for (int i = 0; i < 128; i++) {
        float4 w = wrow[i];
        float4 x = t0[i];
        float4 y = t1[i];
        a0 += w.x * x.x + w.y * x.y + w.z * x.z + w.w * x.w;
        a1 += w.x * y.x + w.y * y.y + w.z * y.z + w.w * y.w;
    }
    const int e = e0 + e_local;
    const float bv = bias[h * D_ + e];
    g_sem[((size_t)bb * H_ + h) * D_ + e]        = a0 + bv;
    g_sem[((size_t)(bb + 16) * H_ + h) * D_ + e] = a1 + bv;
}

// ---------------------------------------------------------------------------
// Kernel 4: known_prompts writer — the HBM-bound kernel (361 MB of stores)
// grid = B_*C_ = 16000, block = 256, pure float4 coalesced stores
// token layout: [prefix(c), domain(b), sem(b,0..7), suffix(c)]  (11 x 512)
// ---------------------------------------------------------------------------
__global__ __launch_bounds__(256) void k_known(const float4* __restrict__ pre,
                                               const float4* __restrict__ suf,
                                               float4* __restrict__ out) {
    const int bc = blockIdx.x;
    const int b  = bc / C_;
    const int c  = bc - b * C_;
    float4* o = out + (size_t)bc * (11 * 128);
    const float4* dom  = ((const float4*)g_dom) + b * 128;
    const float4* sem  = ((const float4*)g_sem) + (size_t)b * H_ * 128;
    const float4* prow = pre + (size_t)c * 128;
    const float4* srow = suf + (size_t)c * 128;

    for (int i = threadIdx.x; i < 11 * 128; i += 256) {
        const int t = i >> 7, j = i & 127;
        float4 v;
        if (t == 0)       v = prow[j];
        else if (t == 1)  v = dom[j];
        else if (t < 10)  v = sem[(t - 2) * 128 + j];
        else              v = srow[j];
        o[i] = v;
    }
}

// ---------------------------------------------------------------------------
// Kernel 5: unknown_prompts writer (tiny)
// token layout: [unk_prefix, domain(b), unk_sem(0..3), unk_suffix]  (7 x 512)
// ---------------------------------------------------------------------------
__global__ __launch_bounds__(256) void k_unknown(const float4* __restrict__ upre,
                                                 const float4* __restrict__ usem,
                                                 const float4* __restrict__ usuf,
                                                 float4* __restrict__ out) {
    const int b = blockIdx.x;
    float4* o = out + (size_t)b * 7 * 128;
    const float4* dom = ((const float4*)g_dom) + b * 128;
    for (int i = threadIdx.x; i < 7 * 128; i += 256) {
        const int t = i >> 7, j = i & 127;
        float4 v;
        if (t == 0)      v = upre[j];
        else if (t == 1) v = dom[j];
        else if (t < 6)  v = usem[(t - 2) * 128 + j];
        else             v = usuf[j];
        o[i] = v;
    }
}

// ---------------------------------------------------------------------------
extern "C" void kernel_launch(void* const* d_in, const int* in_sizes, int n_in,
                              void* d_out, int out_size) {
    const float* patch = (const float*)d_in[0];   // (32,196,512)
    const float* gf    = (const float*)d_in[1];   // (32,512)
    const float* query = (const float*)d_in[2];   // (8,512)
    const float* domW  = (const float*)d_in[3];   // (512,512)
    const float* domb  = (const float*)d_in[4];   // (512,)
    const float* semW  = (const float*)d_in[5];   // (8,512,512)
    const float* semb  = (const float*)d_in[6];   // (8,512)
    const float* usem  = (const float*)d_in[7];   // (4,512)
    const float* pre   = (const float*)d_in[8];   // (500,1,512)
    const float* suf   = (const float*)d_in[9];   // (500,1,512)
    const float* upre  = (const float*)d_in[10];  // (1,512)
    const float* usuf  = (const float*)d_in[11];  // (1,512)

    float* out     = (float*)d_out;
    float* unk_out = out + (size_t)KNOWN_ELEMS;
    float* sem_out = out + (size_t)KNOWN_ELEMS + UNK_ELEMS;  // semantic_tokens

    // 99 KB dynamic smem for k_sem (idempotent; not a stream op, capture-safe)
    cudaFuncSetAttribute(k_sem, cudaFuncAttributeMaxDynamicSharedMemorySize,
                         48 * TPAD * 4);

    k_attn<<<B_, 512>>>(patch, query, sem_out);
    k_dom<<<B_, 256>>>(gf, domW, domb);
    k_sem<<<dim3(32, H_), 256, 48 * TPAD * 4>>>(sem_out, semW, semb);
    k_known<<<B_ * C_, 256>>>((const float4*)pre, (const float4*)suf,
                              (float4*)out);
    k_unknown<<<B_, 256>>>((const float4*)upre, (const float4*)usem,
                           (const float4*)usuf, (float4*)unk_out);
}

// round 3
// speedup vs baseline: 2.5435x; 2.5435x over previous
#include <cuda_runtime.h>

// Shapes (fixed for this problem)
#define B_ 32
#define P_ 196
#define D_ 512
#define H_ 8
#define U_ 4
#define C_ 500

#define KNOWN_ELEMS (B_ * C_ * (H_ + 3) * D_)   // 90,112,000
#define UNK_ELEMS   (B_ * (U_ + 3) * D_)        // 114,688
#define SEM_ELEMS   (B_ * H_ * D_)              // 131,072

// Scratch (device globals — no allocation allowed)
__device__ float g_dom[B_ * D_];          // projected_domain
__device__ float g_sem[B_ * H_ * D_];     // projected_sem
__device__ float g_scores[B_ * P_ * H_];  // raw attention scores

// ---------------------------------------------------------------------------
// Kernel 1: scores[b,p,h] = patch[b,p,:] · query[h,:]
// grid = B_*P_/8 = 784 blocks, 256 threads (8 warps), warp per (b,p) row.
// float4 loads, MLP=4 per warp — full-chip parallel read of 12.8 MB patch.
// ---------------------------------------------------------------------------
__global__ __launch_bounds__(256) void k_scores(const float* __restrict__ patch,
                                                const float* __restrict__ query,
                                                float* __restrict__ scores) {
    __shared__ float4 q_sh[H_ * 128];   // 16 KB
    const int tid = threadIdx.x;
    for (int i = tid; i < H_ * 128; i += 256)
        q_sh[i] = ((const float4*)query)[i];
    __syncthreads();

    const int warp = tid >> 5, lane = tid & 31;
    const int gw = blockIdx.x * 8 + warp;     // 0..6271
    const int b = gw / P_;
    const int p = gw - b * P_;
    const float4* row = (const float4*)(patch + ((size_t)b * P_ + p) * D_);

    float acc[H_];
#pragma unroll
    for (int h = 0; h < H_; h++) acc[h] = 0.f;
#pragma unroll
    for (int i = 0; i < 4; i++) {
        float4 x = row[lane + i * 32];
#pragma unroll
        for (int h = 0; h < H_; h++) {
            float4 q = q_sh[h * 128 + lane + i * 32];
            acc[h] += x.x * q.x + x.y * q.y + x.z * q.z + x.w * q.w;
        }
    }
#pragma unroll
    for (int h = 0; h < H_; h++) {
#pragma unroll
        for (int o = 16; o; o >>= 1)
            acc[h] += __shfl_xor_sync(0xffffffffu, acc[h], o);
    }
    if (lane == 0) {
        float* s = scores + ((size_t)b * P_ + p) * H_;
#pragma unroll
        for (int h = 0; h < H_; h++) s[h] = acc[h];
    }
}

// ---------------------------------------------------------------------------
// Kernel 2: softmax over P (recomputed per block, cheap) + weighted pooling.
// grid = (B_, 4 d-tiles of 128), block = 128. Pool loop unrolled x4 (MLP=4).
// Writes semantic_tokens directly into d_out.
// ---------------------------------------------------------------------------
__global__ __launch_bounds__(128) void k_pool(const float* __restrict__ patch,
                                              const float* __restrict__ scores,
                                              float* __restrict__ sem_out) {
    __shared__ float w_sh[P_ * H_];     // 6.1 KB
    __shared__ float mmax[H_], inv_s[H_];

    const int b = blockIdx.x;
    const int tid = threadIdx.x;
    const float* sc = scores + (size_t)b * P_ * H_;
    for (int i = tid; i < P_ * H_; i += 128) w_sh[i] = sc[i];
    __syncthreads();

    const int warp = tid >> 5, lane = tid & 31;
    // 4 warps, 2 heads each
#pragma unroll
    for (int hh = 0; hh < 2; hh++) {
        const int h = warp * 2 + hh;
        float m = -1e30f;
        for (int p = lane; p < P_; p += 32) m = fmaxf(m, w_sh[p * H_ + h]);
#pragma unroll
        for (int o = 16; o; o >>= 1) m = fmaxf(m, __shfl_xor_sync(0xffffffffu, m, o));
        float s = 0.f;
        for (int p = lane; p < P_; p += 32) s += __expf(w_sh[p * H_ + h] - m);
#pragma unroll
        for (int o = 16; o; o >>= 1) s += __shfl_xor_sync(0xffffffffu, s, o);
        if (lane == 0) { mmax[h] = m; inv_s[h] = 1.f / s; }
    }
    __syncthreads();
    for (int i = tid; i < P_ * H_; i += 128) {
        int h = i & (H_ - 1);
        w_sh[i] = __expf(w_sh[i] - mmax[h]) * inv_s[h];
    }
    __syncthreads();

    // pooling: thread owns one d, accumulates all 8 heads, p unrolled x4
    const int d = blockIdx.y * 128 + tid;
    const float* pb = patch + (size_t)b * P_ * D_ + d;
    float acc[H_];
#pragma unroll
    for (int h = 0; h < H_; h++) acc[h] = 0.f;
    for (int p = 0; p < P_; p += 4) {      // 196 = 49*4
        float x0 = pb[(p + 0) * D_];
        float x1 = pb[(p + 1) * D_];
        float x2 = pb[(p + 2) * D_];
        float x3 = pb[(p + 3) * D_];
#pragma unroll
        for (int h = 0; h < H_; h++) {
            acc[h] = fmaf(w_sh[(p + 0) * H_ + h], x0, acc[h]);
            acc[h] = fmaf(w_sh[(p + 1) * H_ + h], x1, acc[h]);
            acc[h] = fmaf(w_sh[(p + 2) * H_ + h], x2, acc[h]);
            acc[h] = fmaf(w_sh[(p + 3) * H_ + h], x3, acc[h]);
        }
    }
#pragma unroll
    for (int h = 0; h < H_; h++)
        sem_out[((size_t)b * H_ + h) * D_ + d] = acc[h];
}

// ---------------------------------------------------------------------------
// Kernel 3 (fused sem + dom projection):
//   y < 8 :  projected_sem[b,h,e]  = semb[h,e] + T[b,h,:]·semW[h,e,:]
//   y == 8:  projected_domain[b,e] = domb[e]   + gf[b,:]·domW[e,:]
// grid = (32 e-tiles of 16, 9), block = 256; W read once from DRAM.
// dyn smem: T (32 x TPAD) + W-tile (16 x TPAD) = 99 KB
// ---------------------------------------------------------------------------
#define TPAD 516
__global__ __launch_bounds__(256) void k_proj(const float* __restrict__ sem_tok,
                                              const float* __restrict__ semW,
                                              const float* __restrict__ semb,
                                              const float* __restrict__ gf,
                                              const float* __restrict__ domW,
                                              const float* __restrict__ domb) {
    extern __shared__ float sh[];
    float* Tsh = sh;                  // [32][TPAD]
    float* Wsh = sh + 32 * TPAD;      // [16][TPAD]

    const int y  = blockIdx.y;        // 0..8
    const int e0 = blockIdx.x * 16;
    const int tid = threadIdx.x;

    const bool dom = (y == 8);
    const float* Tbase   = dom ? gf : (sem_tok + y * D_);
    const size_t Tstride = dom ? (size_t)D_ : (size_t)H_ * D_;
    const float* Wbase   = dom ? (domW + (size_t)e0 * D_)
                               : (semW + ((size_t)y * D_ + e0) * D_);

    for (int i = tid; i < 32 * 128; i += 256) {
        int b = i >> 7, j = i & 127;
        ((float4*)(Tsh + b * TPAD))[j] =
            ((const float4*)(Tbase + b * Tstride))[j];
    }
    for (int i = tid; i < 16 * 128; i += 256) {
        int e = i >> 7, j = i & 127;
        ((float4*)(Wsh + e * TPAD))[j] = ((const float4*)Wbase)[e * 128 + j];
    }
    __syncthreads();

    const int e_local = tid & 15;
    const int bb      = tid >> 4;     // 0..15 -> handles b = bb, bb+16
    const float4* wrow = (const float4*)(Wsh + e_local * TPAD);
    const float4* t0   = (const float4*)(Tsh + bb * TPAD);
    const float4* t1   = (const float4*)(Tsh + (bb + 16) * TPAD);

    float a0 = 0.f, a1 = 0.f;
#pragma unroll 8
    for (int i = 0; i < 128; i++) {
        float4 w = wrow[i];
        float4 x = t0[i];
        float4 yv = t1[i];
        a0 += w.x * x.x + w.y * x.y + w.z * x.z + w.w * x.w;
        a1 += w.x * yv.x + w.y * yv.y + w.z * yv.z + w.w * yv.w;
    }
    const int e = e0 + e_local;
    if (dom) {
        const float bv = domb[e];
        g_dom[bb * D_ + e]        = a0 + bv;
        g_dom[(bb + 16) * D_ + e] = a1 + bv;
    } else {
        const float bv = semb[y * D_ + e];
        g_sem[((size_t)bb * H_ + y) * D_ + e]        = a0 + bv;
        g_sem[((size_t)(bb + 16) * H_ + y) * D_ + e] = a1 + bv;
    }
}

// ---------------------------------------------------------------------------
// Kernel 4: prompt writer (known + unknown fused) — HBM-bound, 361 MB stores.
// grid = B_*C_ + B_ = 16032, block = 256. Streaming (__stcs) float4 stores.
// known token layout:   [prefix(c), domain(b), sem(b,0..7), suffix(c)] (11x512)
// unknown token layout: [unk_prefix, domain(b), unk_sem(0..3), unk_suffix] (7x512)
// ---------------------------------------------------------------------------
__global__ __launch_bounds__(256) void k_writer(const float4* __restrict__ pre,
                                                const float4* __restrict__ suf,
                                                const float4* __restrict__ upre,
                                                const float4* __restrict__ usem,
                                                const float4* __restrict__ usuf,
                                                float4* __restrict__ out,
                                                float4* __restrict__ unk_out) {
    const int bc = blockIdx.x;
    if (bc < B_ * C_) {
        const int b = bc / C_;
        const int c = bc - b * C_;
        float4* o = out + (size_t)bc * (11 * 128);
        const float4* dm   = ((const float4*)g_dom) + b * 128;
        const float4* sm   = ((const float4*)g_sem) + (size_t)b * H_ * 128;
        const float4* prow = pre + (size_t)c * 128;
        const float4* srow = suf + (size_t)c * 128;
        for (int i = threadIdx.x; i < 11 * 128; i += 256) {
            const int t = i >> 7, j = i & 127;
            float4 v;
            if (t == 0)       v = prow[j];
            else if (t == 1)  v = dm[j];
            else if (t < 10)  v = sm[(t - 2) * 128 + j];
            else              v = srow[j];
            __stcs(&o[i], v);
        }
    } else {
        const int b = bc - B_ * C_;
        float4* o = unk_out + (size_t)b * 7 * 128;
        const float4* dm = ((const float4*)g_dom) + b * 128;
        for (int i = threadIdx.x; i < 7 * 128; i += 256) {
            const int t = i >> 7, j = i & 127;
            float4 v;
            if (t == 0)      v = upre[j];
            else if (t == 1) v = dm[j];
            else if (t < 6)  v = usem[(t - 2) * 128 + j];
            else             v = usuf[j];
            __stcs(&o[i], v);
        }
    }
}

// ---------------------------------------------------------------------------
extern "C" void kernel_launch(void* const* d_in, const int* in_sizes, int n_in,
                              void* d_out, int out_size) {
    const float* patch = (const float*)d_in[0];   // (32,196,512)
    const float* gf    = (const float*)d_in[1];   // (32,512)
    const float* query = (const float*)d_in[2];   // (8,512)
    const float* domW  = (const float*)d_in[3];   // (512,512)
    const float* domb  = (const float*)d_in[4];   // (512,)
    const float* semW  = (const float*)d_in[5];   // (8,512,512)
    const float* semb  = (const float*)d_in[6];   // (8,512)
    const float* usem  = (const float*)d_in[7];   // (4,512)
    const float* pre   = (const float*)d_in[8];   // (500,1,512)
    const float* suf   = (const float*)d_in[9];   // (500,1,512)
    const float* upre  = (const float*)d_in[10];  // (1,512)
    const float* usuf  = (const float*)d_in[11];  // (1,512)

    float* out     = (float*)d_out;
    float* unk_out = out + (size_t)KNOWN_ELEMS;
    float* sem_out = out + (size_t)KNOWN_ELEMS + UNK_ELEMS;  // semantic_tokens

    float* scores_p;
    cudaGetSymbolAddress((void**)&scores_p, g_scores);

    cudaFuncSetAttribute(k_proj, cudaFuncAttributeMaxDynamicSharedMemorySize,
                         48 * TPAD * 4);

    k_scores<<<(B_ * P_) / 8, 256>>>(patch, query, scores_p);
    k_pool<<<dim3(B_, 4), 128>>>(patch, scores_p, sem_out);
    k_proj<<<dim3(32, 9), 256, 48 * TPAD * 4>>>(sem_out, semW, semb,
                                                gf, domW, domb);
    k_writer<<<B_ * C_ + B_, 256>>>((const float4*)pre, (const float4*)suf,
                                    (const float4*)upre, (const float4*)usem,
                                    (const float4*)usuf,
                                    (float4*)out, (float4*)unk_out);
}